// round 3
// baseline (speedup 1.0000x reference)
#include <cuda_runtime.h>
#include <math.h>

#define KT     100
#define VDIM   8192
#define TOPN   20
#define NWORDS (VDIM / 32)    // 256 bitmask words
#define SLICES 8              // column slices per topic
#define NB     (KT * SLICES)  // 800 blocks for loss phases

// ---------------- scratch (device globals; zero-initialized at load) --------
__device__ float    g_p[KT * TOPN];
__device__ int      g_idx[KT * TOPN];
__device__ float2   g_stat[KT];            // (rowmax, invsum) of softmax(beta)
__device__ unsigned g_U1[NWORDS];          // v in >=1 topic's top-20
__device__ unsigned g_U2[NWORDS];          // v in >=2 topics' top-20
__device__ unsigned g_mn[KT], g_mx[KT];    // per-topic min/max of M (uint-ordered)
__device__ float    g_M[KT * VDIM];        // 3.2 MB staged M
__device__ double   g_partial[NB * 2];
__device__ unsigned g_done;

// ============ kernel 1: all-register top-20 + softmax stats =================
__global__ void __launch_bounds__(256) topk_kernel(const float* __restrict__ beta) {
    __shared__ float candv[8 * TOPN];
    __shared__ int   candi[8 * TOPN];
    __shared__ float topv[TOPN];
    __shared__ int   topi[TOPN];
    __shared__ float wsum[8];

    const int k    = blockIdx.x;
    const int tid  = threadIdx.x;
    const int warp = tid >> 5;
    const int lane = tid & 31;

    if (tid == 0) { g_mn[k] = 0x7F800000u; g_mx[k] = 0u; }  // +inf / 0 for lossA atomics

    // each lane holds 32 values of its warp's 1024-col segment in registers
    const int base = warp * 1024;
    const float4* b4 = (const float4*)(beta + (size_t)k * VDIM + base);
    float rv[32];
    #pragma unroll
    for (int i = 0; i < 8; ++i) {
        float4 t = __ldg(b4 + i * 32 + lane);
        rv[i * 4 + 0] = t.x; rv[i * 4 + 1] = t.y;
        rv[i * 4 + 2] = t.z; rv[i * 4 + 3] = t.w;
    }
    // global col of rv[e] = base + (e>>2)*128 + lane*4 + (e&3); ascending in e

    // cached per-lane argmax (strict > keeps lowest index)
    unsigned used = 0u;
    float bv = -INFINITY; int bi = 0x7fffffff; int be = 0;
    #pragma unroll
    for (int e = 0; e < 32; ++e) {
        int idx = base + (e >> 2) * 128 + lane * 4 + (e & 3);
        if (rv[e] > bv) { bv = rv[e]; bi = idx; be = e; }
    }

    // per-warp top-20 extraction
    for (int it = 0; it < TOPN; ++it) {
        float mv = bv; int mi = bi;
        #pragma unroll
        for (int o = 16; o; o >>= 1) {
            float ov = __shfl_xor_sync(0xFFFFFFFFu, mv, o);
            int   oi = __shfl_xor_sync(0xFFFFFFFFu, mi, o);
            if (ov > mv || (ov == mv && oi < mi)) { mv = ov; mi = oi; }
        }
        if (lane == 0) { candv[warp * TOPN + it] = mv; candi[warp * TOPN + it] = mi; }
        if (bi == mi) {                 // this lane owned the winner
            used |= 1u << be;
            bv = -INFINITY; bi = 0x7fffffff;
            #pragma unroll
            for (int e = 0; e < 32; ++e) {
                if (!((used >> e) & 1u) && rv[e] > bv) {
                    bv = rv[e];
                    bi = base + (e >> 2) * 128 + lane * 4 + (e & 3);
                    be = e;
                }
            }
        }
        __syncwarp();
    }
    __syncthreads();

    // warp 0 merges 160 candidates -> global top-20
    if (warp == 0) {
        for (int it = 0; it < TOPN; ++it) {
            float mv = -INFINITY; int mi = 0x7fffffff; int ms = -1;
            #pragma unroll
            for (int i = 0; i < 5; ++i) {
                int c = lane + i * 32;
                float x = candv[c]; int ix = candi[c];
                if (x > mv || (x == mv && ix < mi)) { mv = x; mi = ix; ms = c; }
            }
            #pragma unroll
            for (int o = 16; o; o >>= 1) {
                float ov = __shfl_xor_sync(0xFFFFFFFFu, mv, o);
                int   oi = __shfl_xor_sync(0xFFFFFFFFu, mi, o);
                int   os = __shfl_xor_sync(0xFFFFFFFFu, ms, o);
                if (ov > mv || (ov == mv && oi < mi)) { mv = ov; mi = oi; ms = os; }
            }
            if (lane == 0) { topv[it] = mv; topi[it] = mi; candv[ms] = -INFINITY; }
            __syncwarp();
        }
    }
    __syncthreads();

    // full softmax denominator: rowmax is the first global winner
    const float rowmax = topv[0];
    float s = 0.f;
    #pragma unroll
    for (int e = 0; e < 32; ++e) s += expf(rv[e] - rowmax);
    #pragma unroll
    for (int o = 16; o; o >>= 1) s += __shfl_xor_sync(0xFFFFFFFFu, s, o);
    if (lane == 0) wsum[warp] = s;
    __syncthreads();

    if (warp == 0) {
        s = wsum[lane & 7];
        #pragma unroll
        for (int o = 4; o; o >>= 1) s += __shfl_xor_sync(0xFFFFFFFFu, s, o);
        // masked softmax over the 20 survivors (rest underflow to exact 0)
        float e20 = (lane < TOPN) ? expf(topv[lane] - rowmax) : 0.f;
        float ps = e20;
        #pragma unroll
        for (int o = 16; o; o >>= 1) ps += __shfl_xor_sync(0xFFFFFFFFu, ps, o);
        const float invp = 1.0f / ps;
        if (lane < TOPN) {
            g_p[k * TOPN + lane]   = e20 * invp;
            int ix = topi[lane];
            g_idx[k * TOPN + lane] = ix;
            unsigned w = (unsigned)ix >> 5, mb = 1u << (ix & 31);
            unsigned old = atomicOr(&g_U1[w], mb);
            if (old & mb) atomicOr(&g_U2[w], mb);
        }
        if (lane == 0) g_stat[k] = make_float2(rowmax, 1.0f / s);
    }
}

// ===== kernel 2 (phase A): sparse p@W slice, store M, merge min/max =========
__global__ void __launch_bounds__(256) lossA_kernel(const float* __restrict__ Wmat) {
    __shared__ float sp[TOPN];
    __shared__ int   si[TOPN];
    __shared__ float r1[8], r2[8];

    const int b    = blockIdx.x;
    const int k    = b >> 3;
    const int sl   = b & 7;
    const int tid  = threadIdx.x;
    const int warp = tid >> 5;
    const int lane = tid & 31;

    if (tid < TOPN) { sp[tid] = g_p[k * TOPN + tid]; si[tid] = g_idx[k * TOPN + tid]; }
    __syncthreads();

    const int v0 = sl * 1024 + tid * 4;
    float ax = 0.f, ay = 0.f, az = 0.f, aw = 0.f;
    #pragma unroll
    for (int j = 0; j < TOPN; ++j) {
        const float pj = sp[j];
        float4 w = __ldg((const float4*)(Wmat + (size_t)si[j] * VDIM + v0));
        ax = fmaf(pj, w.x, ax); ay = fmaf(pj, w.y, ay);
        az = fmaf(pj, w.z, az); aw = fmaf(pj, w.w, aw);
    }
    *(float4*)(g_M + (size_t)k * VDIM + v0) = make_float4(ax, ay, az, aw);

    float mn = fminf(fminf(ax, ay), fminf(az, aw));
    float mx = fmaxf(fmaxf(ax, ay), fmaxf(az, aw));
    #pragma unroll
    for (int o = 16; o; o >>= 1) {
        mn = fminf(mn, __shfl_xor_sync(0xFFFFFFFFu, mn, o));
        mx = fmaxf(mx, __shfl_xor_sync(0xFFFFFFFFu, mx, o));
    }
    if (lane == 0) { r1[warp] = mn; r2[warp] = mx; }
    __syncthreads();
    if (warp == 0) {
        mn = r1[lane & 7]; mx = r2[lane & 7];
        #pragma unroll
        for (int o = 4; o; o >>= 1) {
            mn = fminf(mn, __shfl_xor_sync(0xFFFFFFFFu, mn, o));
            mx = fmaxf(mx, __shfl_xor_sync(0xFFFFFFFFu, mx, o));
        }
        if (lane == 0) {
            // all M values are >= 0, so uint ordering == float ordering
            atomicMin(&g_mn[k], __float_as_uint(mn));
            atomicMax(&g_mx[k], __float_as_uint(mx));
        }
    }
}

// ===== kernel 3 (phase B): Wc, loss, Md split, fused final reduction ========
__global__ void __launch_bounds__(256) lossB_kernel(
    const float* __restrict__ beta, const int* __restrict__ epoch,
    float* __restrict__ out)
{
    __shared__ int    si[TOPN];
    __shared__ float  r1[8], r2[8];
    __shared__ double d1[8], d2[8];
    __shared__ int    is_last;

    const int b    = blockIdx.x;
    const int k    = b >> 3;
    const int sl   = b & 7;
    const int tid  = threadIdx.x;
    const int warp = tid >> 5;
    const int lane = tid & 31;

    if (tid < TOPN) si[tid] = g_idx[k * TOPN + tid];
    __syncthreads();

    const int v0      = sl * 1024 + tid * 4;
    const unsigned word  = (unsigned)v0 >> 5;
    const int      shift = v0 & 31;

    unsigned ow = 0u;
    #pragma unroll
    for (int j = 0; j < TOPN; ++j)
        if (((unsigned)si[j] >> 5) == word) ow |= 1u << (si[j] & 31);

    const float mn   = __uint_as_float(g_mn[k]);
    const float mx   = __uint_as_float(g_mx[k]);
    const float invr = 1.0f / (mx - mn);
    const float2 st  = g_stat[k];

    float4 m  = *(const float4*)(g_M + (size_t)k * VDIM + v0);
    float4 bt = __ldg((const float4*)(beta + (size_t)k * VDIM + v0));
    const unsigned u1 = g_U1[word], u2 = g_U2[word];

    float mv[4] = {m.x, m.y, m.z, m.w};
    float bv[4] = {bt.x, bt.y, bt.z, bt.w};
    float pos = 0.f, neg = 0.f;
    #pragma unroll
    for (int c = 0; c < 4; ++c) {
        const float wc = 1.0f - (mv[c] - mn) * invr;
        const float sv = expf(bv[c] - st.x) * st.y;
        const float l  = 100.0f * sv * sv * wc;
        const unsigned mb = 1u << (shift + c);
        const bool md = (ow & mb) ? (u2 & mb) : (u1 & mb);
        if (md) pos += l; else neg += l;
    }
    #pragma unroll
    for (int o = 16; o; o >>= 1) {
        pos += __shfl_xor_sync(0xFFFFFFFFu, pos, o);
        neg += __shfl_xor_sync(0xFFFFFFFFu, neg, o);
    }
    if (lane == 0) { r1[warp] = pos; r2[warp] = neg; }
    __syncthreads();
    if (warp == 0) {
        pos = r1[lane & 7]; neg = r2[lane & 7];
        #pragma unroll
        for (int o = 4; o; o >>= 1) {
            pos += __shfl_xor_sync(0xFFFFFFFFu, pos, o);
            neg += __shfl_xor_sync(0xFFFFFFFFu, neg, o);
        }
    }

    if (tid == 0) {
        g_partial[2 * b]     = (double)pos;
        g_partial[2 * b + 1] = (double)neg;
        __threadfence();
        unsigned r = atomicAdd(&g_done, 1u);
        is_last = (r == NB - 1);
    }
    __syncthreads();

    if (is_last) {
        __threadfence();
        double p = 0.0, n = 0.0;
        for (int i = tid; i < NB; i += 256) {
            p += g_partial[2 * i];
            n += g_partial[2 * i + 1];
        }
        #pragma unroll
        for (int o = 16; o; o >>= 1) {
            p += __shfl_xor_sync(0xFFFFFFFFu, p, o);
            n += __shfl_xor_sync(0xFFFFFFFFu, n, o);
        }
        if (lane == 0) { d1[warp] = p; d2[warp] = n; }
        __syncthreads();
        if (warp == 0) {
            p = d1[lane & 7]; n = d2[lane & 7];
            #pragma unroll
            for (int o = 4; o; o >>= 1) {
                p += __shfl_xor_sync(0xFFFFFFFFu, p, o);
                n += __shfl_xor_sync(0xFFFFFFFFu, n, o);
            }
            if (lane == 0) {
                const int e = *epoch;                 // warmup = 100, delta = 1.0
                const float lam = (e < 100) ? (float)e : 100.0f;
                out[0] = lam * (float)((p * 0.7 + n * 0.3) * 2.0);
                g_done = 0;                           // reset for next replay
            }
        }
        g_U1[tid] = 0u;   // NWORDS == 256 == blockDim
        g_U2[tid] = 0u;
    }
}

// ---------------- launch -----------------------------------------------------
extern "C" void kernel_launch(void* const* d_in, const int* in_sizes, int n_in,
                              void* d_out, int out_size) {
    const float* beta  = (const float*)d_in[0];
    const float* Wmat  = (const float*)d_in[1];
    const int*   epoch = (const int*)d_in[2];
    float* out = (float*)d_out;

    topk_kernel<<<KT, 256>>>(beta);
    lossA_kernel<<<NB, 256>>>(Wmat);
    lossB_kernel<<<NB, 256>>>(beta, epoch, out);
}

// round 4
// speedup vs baseline: 1.1230x; 1.1230x over previous
#include <cuda_runtime.h>
#include <math.h>

#define KT     100
#define VDIM   8192
#define TOPN   20
#define NWORDS (VDIM / 32)    // 256 bitmask words
#define SLICES 8
#define NB     (KT * SLICES)  // 800 blocks for loss phases
#define CANDMAX 2048

// ---------------- scratch (device globals; zero-initialized at load) --------
__device__ float    g_p[KT * TOPN];
__device__ int      g_idx[KT * TOPN];
__device__ float    g_rowmax[KT];
__device__ unsigned g_U1[NWORDS];          // v in >=1 topic's top-20
__device__ unsigned g_U2[NWORDS];          // v in >=2 topics' top-20
__device__ unsigned g_mn[KT], g_mx[KT];    // per-topic min/max of M (uint-ordered)
__device__ float    g_M[KT * VDIM];        // 3.2 MB staged M
__device__ float    g_rowsum[NB];          // per-(topic,slice) sum of exp(beta-rowmax)
__device__ double   g_partial[NB * 2];     // per-(topic,slice) UNNORMALIZED (pos, neg)
__device__ unsigned g_done;

// ============ kernel 1: threshold-prune top-20 + masked softmax p ===========
__global__ void __launch_bounds__(256) topk_kernel(const float* __restrict__ beta) {
    __shared__ float smax[256];
    __shared__ float cval[CANDMAX];
    __shared__ int   cidx[CANDMAX];
    __shared__ int   ccnt;
    __shared__ float sthr[2];             // [0]=tau, [1]=rowmax
    __shared__ float topv_s[TOPN];
    __shared__ int   topi_s[TOPN];

    const int k    = blockIdx.x;
    const int tid  = threadIdx.x;
    const int warp = tid >> 5;
    const int lane = tid & 31;

    if (tid == 0) { g_mn[k] = 0x7F800000u; g_mx[k] = 0u; ccnt = 0; }

    // each lane holds 32 values of its warp's 1024-col segment in registers
    // idx(e) = base + (e>>2)*128 + lane*4 + (e&3)
    const int base = warp * 1024;
    const float4* b4 = (const float4*)(beta + (size_t)k * VDIM + base);
    float rv[32];
    #pragma unroll
    for (int i = 0; i < 8; ++i) {
        float4 t = __ldg(b4 + i * 32 + lane);
        rv[i * 4 + 0] = t.x; rv[i * 4 + 1] = t.y;
        rv[i * 4 + 2] = t.z; rv[i * 4 + 3] = t.w;
    }

    // per-thread max -> smem
    float tm = rv[0];
    #pragma unroll
    for (int e = 1; e < 32; ++e) tm = fmaxf(tm, rv[e]);
    smax[tid] = tm;
    __syncthreads();

    // warp 0: tau = 20th largest of the 256 thread-maxima (tau <= x20 provably)
    if (warp == 0) {
        float v[8];
        #pragma unroll
        for (int i = 0; i < 8; ++i) v[i] = smax[lane + 32 * i];
        unsigned used = 0u;
        float tau = 0.f, rmax = 0.f;
        for (int r = 0; r < TOPN; ++r) {
            float lm = -INFINITY; int li = -1;
            #pragma unroll
            for (int i = 0; i < 8; ++i)
                if (!((used >> i) & 1u) && v[i] > lm) { lm = v[i]; li = i; }
            float wm = lm;
            #pragma unroll
            for (int o = 16; o; o >>= 1) wm = fmaxf(wm, __shfl_xor_sync(0xFFFFFFFFu, wm, o));
            if (r == 0) rmax = wm;
            tau = wm;
            unsigned b = __ballot_sync(0xFFFFFFFFu, lm == wm);
            if (lane == (int)(__ffs(b) - 1)) used |= 1u << li;
        }
        if (lane == 0) { sthr[0] = tau; sthr[1] = rmax; }
    }
    __syncthreads();
    const float tau = sthr[0];

    // collect candidates (val >= tau); guaranteed >= 20 of them
    #pragma unroll
    for (int e = 0; e < 32; ++e) {
        if (rv[e] >= tau) {
            int p = atomicAdd(&ccnt, 1);
            if (p < CANDMAX) {
                cval[p] = rv[e];
                cidx[p] = base + (e >> 2) * 128 + lane * 4 + (e & 3);
            }
        }
    }
    __syncthreads();

    // warp 0: exact top-20 by (val desc, idx asc), sort by idx, softmax p
    if (warp == 0) {
        const int cnt = min(ccnt, CANDMAX);
        for (int r = 0; r < TOPN; ++r) {
            float lm = -INFINITY; int li = 0x7fffffff; int ls = -1;
            for (int i = lane; i < cnt; i += 32) {
                float x = cval[i]; int ix = cidx[i];
                if (x > lm || (x == lm && ix < li)) { lm = x; li = ix; ls = i; }
            }
            #pragma unroll
            for (int o = 16; o; o >>= 1) {
                float ov = __shfl_xor_sync(0xFFFFFFFFu, lm, o);
                int   oi = __shfl_xor_sync(0xFFFFFFFFu, li, o);
                int   os = __shfl_xor_sync(0xFFFFFFFFu, ls, o);
                if (ov > lm || (ov == lm && oi < li)) { lm = ov; li = oi; ls = os; }
            }
            if (lane == 0) { topv_s[r] = lm; topi_s[r] = li; cval[ls] = -INFINITY; }
            __syncwarp();
        }

        // sort the 20 by index (rank = #smaller indices; a permutation)
        float myv = 0.f; int myi = 0x7fffffff;
        if (lane < TOPN) { myv = topv_s[lane]; myi = topi_s[lane]; }
        int rank = 0;
        #pragma unroll
        for (int j = 0; j < TOPN; ++j) rank += (topi_s[j] < myi);
        __syncwarp();
        if (lane < TOPN) { topv_s[rank] = myv; topi_s[rank] = myi; }
        __syncwarp();

        // masked softmax over the 20 (everything else underflows to exact 0)
        const float rmax = sthr[1];
        float e20 = (lane < TOPN) ? expf(topv_s[lane] - rmax) : 0.f;
        float ps = e20;
        #pragma unroll
        for (int o = 16; o; o >>= 1) ps += __shfl_xor_sync(0xFFFFFFFFu, ps, o);
        const float invp = 1.0f / ps;

        if (lane < TOPN) {
            g_p[k * TOPN + lane]   = e20 * invp;
            int ix = topi_s[lane];
            g_idx[k * TOPN + lane] = ix;
            unsigned w = (unsigned)ix >> 5, mb = 1u << (ix & 31);
            unsigned old = atomicOr(&g_U1[w], mb);
            if (old & mb) atomicOr(&g_U2[w], mb);
        }
        if (lane == 0) g_rowmax[k] = rmax;
    }
}

// ===== kernel 2 (phase A): sparse p@W slice, store M, merge min/max =========
__global__ void __launch_bounds__(256) lossA_kernel(const float* __restrict__ Wmat) {
    __shared__ float sp[TOPN];
    __shared__ int   si[TOPN];
    __shared__ float r1[8], r2[8];

    const int b    = blockIdx.x;
    const int k    = b >> 3;
    const int sl   = b & 7;
    const int tid  = threadIdx.x;
    const int warp = tid >> 5;
    const int lane = tid & 31;

    if (tid < TOPN) { sp[tid] = g_p[k * TOPN + tid]; si[tid] = g_idx[k * TOPN + tid]; }
    __syncthreads();

    const int v0 = sl * 1024 + tid * 4;
    float ax = 0.f, ay = 0.f, az = 0.f, aw = 0.f;
    #pragma unroll
    for (int j = 0; j < TOPN; ++j) {
        const float pj = sp[j];
        float4 w = __ldg((const float4*)(Wmat + (size_t)si[j] * VDIM + v0));
        ax = fmaf(pj, w.x, ax); ay = fmaf(pj, w.y, ay);
        az = fmaf(pj, w.z, az); aw = fmaf(pj, w.w, aw);
    }
    *(float4*)(g_M + (size_t)k * VDIM + v0) = make_float4(ax, ay, az, aw);

    float mn = fminf(fminf(ax, ay), fminf(az, aw));
    float mx = fmaxf(fmaxf(ax, ay), fmaxf(az, aw));
    #pragma unroll
    for (int o = 16; o; o >>= 1) {
        mn = fminf(mn, __shfl_xor_sync(0xFFFFFFFFu, mn, o));
        mx = fmaxf(mx, __shfl_xor_sync(0xFFFFFFFFu, mx, o));
    }
    if (lane == 0) { r1[warp] = mn; r2[warp] = mx; }
    __syncthreads();
    if (warp == 0) {
        mn = r1[lane & 7]; mx = r2[lane & 7];
        #pragma unroll
        for (int o = 4; o; o >>= 1) {
            mn = fminf(mn, __shfl_xor_sync(0xFFFFFFFFu, mn, o));
            mx = fmaxf(mx, __shfl_xor_sync(0xFFFFFFFFu, mx, o));
        }
        if (lane == 0) {
            // all M values >= 0, so uint ordering == float ordering
            atomicMin(&g_mn[k], __float_as_uint(mn));
            atomicMax(&g_mx[k], __float_as_uint(mx));
        }
    }
}

// ===== kernel 3 (phase B): Wc, unnormalized loss, rowsum, fused final =======
__global__ void __launch_bounds__(256) lossB_kernel(
    const float* __restrict__ beta, const int* __restrict__ epoch,
    float* __restrict__ out)
{
    __shared__ int    si[TOPN];
    __shared__ float  r1[8], r2[8], r3[8];
    __shared__ double d1[8], d2[8];
    __shared__ int    is_last;

    const int b    = blockIdx.x;
    const int k    = b >> 3;
    const int sl   = b & 7;
    const int tid  = threadIdx.x;
    const int warp = tid >> 5;
    const int lane = tid & 31;

    if (tid < TOPN) si[tid] = g_idx[k * TOPN + tid];
    __syncthreads();

    const int v0         = sl * 1024 + tid * 4;
    const unsigned word  = (unsigned)v0 >> 5;
    const int      shift = v0 & 31;

    unsigned ow = 0u;
    #pragma unroll
    for (int j = 0; j < TOPN; ++j)
        if (((unsigned)si[j] >> 5) == word) ow |= 1u << (si[j] & 31);

    const float mn   = __uint_as_float(g_mn[k]);
    const float mx   = __uint_as_float(g_mx[k]);
    const float invr = 1.0f / (mx - mn);
    const float rmax = g_rowmax[k];

    float4 m  = *(const float4*)(g_M + (size_t)k * VDIM + v0);
    float4 bt = __ldg((const float4*)(beta + (size_t)k * VDIM + v0));
    const unsigned u1 = g_U1[word], u2 = g_U2[word];

    float mv[4] = {m.x, m.y, m.z, m.w};
    float bv[4] = {bt.x, bt.y, bt.z, bt.w};
    float pos = 0.f, neg = 0.f, es = 0.f;
    #pragma unroll
    for (int c = 0; c < 4; ++c) {
        const float wc = 1.0f - (mv[c] - mn) * invr;
        const float e  = expf(bv[c] - rmax);       // unnormalized softmax numerator
        es += e;
        const float l  = 100.0f * e * e * wc;      // scaled by 1/S^2 at the end
        const unsigned mb = 1u << (shift + c);
        const bool md = (ow & mb) ? (u2 & mb) : (u1 & mb);
        if (md) pos += l; else neg += l;
    }
    #pragma unroll
    for (int o = 16; o; o >>= 1) {
        pos += __shfl_xor_sync(0xFFFFFFFFu, pos, o);
        neg += __shfl_xor_sync(0xFFFFFFFFu, neg, o);
        es  += __shfl_xor_sync(0xFFFFFFFFu, es, o);
    }
    if (lane == 0) { r1[warp] = pos; r2[warp] = neg; r3[warp] = es; }
    __syncthreads();
    if (warp == 0) {
        pos = r1[lane & 7]; neg = r2[lane & 7]; es = r3[lane & 7];
        #pragma unroll
        for (int o = 4; o; o >>= 1) {
            pos += __shfl_xor_sync(0xFFFFFFFFu, pos, o);
            neg += __shfl_xor_sync(0xFFFFFFFFu, neg, o);
            es  += __shfl_xor_sync(0xFFFFFFFFu, es, o);
        }
    }

    if (tid == 0) {
        g_partial[2 * b]     = (double)pos;
        g_partial[2 * b + 1] = (double)neg;
        g_rowsum[b]          = es;
        __threadfence();
        unsigned r = atomicAdd(&g_done, 1u);
        is_last = (r == NB - 1);
    }
    __syncthreads();

    if (is_last) {
        __threadfence();
        double P = 0.0, N = 0.0;
        for (int t = tid; t < KT; t += 256) {        // only tid<100 active
            double S = 0.0, p = 0.0, n = 0.0;
            #pragma unroll
            for (int s2 = 0; s2 < SLICES; ++s2) {
                S += (double)g_rowsum[t * SLICES + s2];
                p += g_partial[2 * (t * SLICES + s2)];
                n += g_partial[2 * (t * SLICES + s2) + 1];
            }
            const double inv = 1.0 / (S * S);
            P += p * inv; N += n * inv;
        }
        #pragma unroll
        for (int o = 16; o; o >>= 1) {
            P += __shfl_xor_sync(0xFFFFFFFFu, P, o);
            N += __shfl_xor_sync(0xFFFFFFFFu, N, o);
        }
        if (lane == 0) { d1[warp] = P; d2[warp] = N; }
        __syncthreads();
        if (warp == 0) {
            P = d1[lane & 7]; N = d2[lane & 7];
            #pragma unroll
            for (int o = 4; o; o >>= 1) {
                P += __shfl_xor_sync(0xFFFFFFFFu, P, o);
                N += __shfl_xor_sync(0xFFFFFFFFu, N, o);
            }
            if (lane == 0) {
                const int e = *epoch;                 // warmup = 100, delta = 1.0
                const float lam = (e < 100) ? (float)e : 100.0f;
                out[0] = lam * (float)((P * 0.7 + N * 0.3) * 2.0);
                g_done = 0;                           // reset for next replay
            }
        }
        g_U1[tid] = 0u;   // NWORDS == 256 == blockDim
        g_U2[tid] = 0u;
    }
}

// ---------------- launch -----------------------------------------------------
extern "C" void kernel_launch(void* const* d_in, const int* in_sizes, int n_in,
                              void* d_out, int out_size) {
    const float* beta  = (const float*)d_in[0];
    const float* Wmat  = (const float*)d_in[1];
    const int*   epoch = (const int*)d_in[2];
    float* out = (float*)d_out;

    topk_kernel<<<KT, 256>>>(beta);
    lossA_kernel<<<NB, 256>>>(Wmat);
    lossB_kernel<<<NB, 256>>>(beta, epoch, out);
}